// round 15
// baseline (speedup 1.0000x reference)
#include <cuda_runtime.h>
#include <cuda_bf16.h>
#include <cuda_fp16.h>
#include <cstdint>
#include <cstddef>

#define NIMG    8
#define NCH     192
#define KCODES  1024
#define NPIX    32768
#define NELEM   (NPIX * KCODES)     // 33,554,432 gumbel draws

// ----------------------------- device scratch ------------------------------
__device__ __align__(256) float g_B[NCH * NCH];     // (wk^T wq) * t1/sqrt(192), [c'][c]
__device__ __align__(256) float g_wvT[NCH * NCH];   // wv transposed: [c'][o]
__device__ __align__(256) float g_v[KCODES * NCH];  // value matrix [j][o]
__device__ int g_idx[NPIX];                         // gumbel argmax per pixel
__device__ float g_u[NELEM];                        // uniform draws (128 MiB)

// fp16 2-way mantissa splits (A = latent, B = kk * 64)
__device__ __align__(256) __half g_A0[NPIX * NCH];
__device__ __align__(256) __half g_A1[NPIX * NCH];
__device__ __align__(256) __half g_B0[KCODES * NCH];
__device__ __align__(256) __half g_B1[KCODES * NCH];

// ----------------------------- PTX helpers (baseline ISA only) -------------
__device__ __forceinline__ uint32_t smem_to_u32(const void* p) {
    uint32_t a;
    asm("{ .reg .u64 t; cvta.to.shared.u64 t, %1; cvt.u32.u64 %0, t; }" : "=r"(a) : "l"(p));
    return a;
}
#define LDSM_X4(r0, r1, r2, r3, addr) \
    asm volatile("ldmatrix.sync.aligned.m8n8.x4.shared.b16 {%0,%1,%2,%3}, [%4];" \
        : "=r"(r0), "=r"(r1), "=r"(r2), "=r"(r3) : "r"(addr))
#define MMA16816(c, a, b) \
    asm volatile("mma.sync.aligned.m16n8k16.row.col.f32.f16.f16.f32 " \
        "{%0,%1,%2,%3},{%4,%5,%6,%7},{%8,%9},{%0,%1,%2,%3};" \
        : "+f"((c)[0]), "+f"((c)[1]), "+f"((c)[2]), "+f"((c)[3]) \
        : "r"((a)[0]), "r"((a)[1]), "r"((a)[2]), "r"((a)[3]), "r"((b)[0]), "r"((b)[1]))
#define CP16(dst, src) \
    asm volatile("cp.async.cg.shared.global [%0], [%1], 16;" :: "r"(dst), "l"(src))
#define CP_COMMIT() asm volatile("cp.async.commit_group;" ::: "memory")
#define CP_WAIT(n)  asm volatile("cp.async.wait_group %0;" :: "n"(n) : "memory")

// ----------------------------- math helpers --------------------------------
// Threefry-2x32, 20 rounds, key = (0, 42)
__device__ __forceinline__ void threefry42(uint32_t c0, uint32_t c1,
                                           uint32_t& o0, uint32_t& o1) {
    const uint32_t ks0 = 0u;
    const uint32_t ks1 = 42u;
    const uint32_t ks2 = 0x1BD11BDAu ^ 42u;
    uint32_t x0 = c0 + ks0;
    uint32_t x1 = c1 + ks1;
#define TFR(r) { x0 += x1; x1 = __funnelshift_l(x1, x1, (r)); x1 ^= x0; }
    TFR(13) TFR(15) TFR(26) TFR(6)
    x0 += ks1; x1 += ks2 + 1u;
    TFR(17) TFR(29) TFR(16) TFR(24)
    x0 += ks2; x1 += ks0 + 2u;
    TFR(13) TFR(15) TFR(26) TFR(6)
    x0 += ks0; x1 += ks1 + 3u;
    TFR(17) TFR(29) TFR(16) TFR(24)
    x0 += ks1; x1 += ks2 + 4u;
    TFR(13) TFR(15) TFR(26) TFR(6)
    x0 += ks2; x1 += ks0 + 5u;
#undef TFR
    o0 = x0; o1 = x1;
}
__device__ __forceinline__ float gumbel_of_u(float u) {
    float w = -log1pf(u - 1.0f);
    return -logf(w);
}
__device__ __forceinline__ unsigned long long packkey(float v, int j) {
    uint32_t u = __float_as_uint(v);
    u = ((int)u >= 0) ? (u | 0x80000000u) : ~u;
    return ((unsigned long long)u << 32) | (uint32_t)(1023 - j);
}
__device__ __forceinline__ void split2h(float a, __half& h0, __half& h1) {
    h0 = __float2half_rn(a);
    float r = a - __half2float(h0);
    h1 = __float2half_rn(r);
}

// ----------------------------- prep kernels --------------------------------
__global__ __launch_bounds__(192) void aq_prep1(const float* __restrict__ wq,
                                                const float* __restrict__ wk,
                                                const float* __restrict__ wv,
                                                const float* __restrict__ t1) {
    const int cp = blockIdx.x;
    const int c  = threadIdx.x;
    const float s = t1[0] / 13.856406460551018f;  // t1 / sqrt(192)
    float acc = 0.0f;
    for (int o = 0; o < NCH; o++)
        acc = fmaf(wk[o * NCH + cp], wq[o * NCH + c], acc);
    g_B[cp * NCH + c]   = acc * s;
    g_wvT[cp * NCH + c] = wv[c * NCH + cp];
}

// kk = codebook @ B, scaled x64, emitted as fp16 splits; v = codebook @ wv^T
__global__ __launch_bounds__(192) void aq_prep2(const float* __restrict__ codebook) {
    __shared__ float cb[8][NCH];
    const int j0 = blockIdx.x * 8;
    const int t  = threadIdx.x;
    for (int idx = t; idx < 8 * NCH; idx += 192) {
        int r = idx / NCH, c = idx % NCH;
        cb[r][c] = codebook[(size_t)(j0 + r) * NCH + c];
    }
    __syncthreads();
    float a1[8], a2[8];
#pragma unroll
    for (int r = 0; r < 8; r++) { a1[r] = 0.0f; a2[r] = 0.0f; }
    for (int cp = 0; cp < NCH; cp++) {
        float b = g_B[cp * NCH + t];
        float w = g_wvT[cp * NCH + t];
#pragma unroll
        for (int r = 0; r < 8; r++) {
            a1[r] = fmaf(cb[r][cp], b, a1[r]);
            a2[r] = fmaf(cb[r][cp], w, a2[r]);
        }
    }
#pragma unroll
    for (int r = 0; r < 8; r++) {
        size_t o = (size_t)(j0 + r) * NCH + t;
        __half s0, s1;
        split2h(a1[r] * 64.0f, s0, s1);   // scale keeps s1 in fp16 normal range
        g_B0[o] = s0; g_B1[o] = s1;
        g_v[o] = a2[r];
    }
}

// transpose + split: latent [n][c][hw] fp32 -> g_A{0,1} [p][c] fp16
__global__ __launch_bounds__(256) void aq_convA(const float* __restrict__ latent) {
    __shared__ float tile[32][33];
    const int hw0 = blockIdx.x * 32;
    const int c0  = blockIdx.y * 32;
    const int n   = blockIdx.z;
    const int tx  = threadIdx.x;       // 0..31
    const int ty  = threadIdx.y;       // 0..7
#pragma unroll
    for (int k = 0; k < 4; k++) {
        int c = c0 + ty + k * 8;
        tile[ty + k * 8][tx] = latent[((size_t)n * NCH + c) * 4096 + hw0 + tx];
    }
    __syncthreads();
#pragma unroll
    for (int k = 0; k < 4; k++) {
        int hw = hw0 + ty + k * 8;
        size_t o = (size_t)(n * 4096 + hw) * NCH + c0 + tx;
        __half s0, s1;
        split2h(tile[tx][ty + k * 8], s0, s1);
        g_A0[o] = s0; g_A1[o] = s1;
    }
}

// -------------- hash: dependency-free gumbel uniform generation ------------
// Runs concurrently with the GEMM (alu-bound vs tensor-bound, no deps).
// __maxnreg__(32): one 8-warp CTA fits beside 2 gemm CTAs (57344+8192 regs)
// and 8 warps saturate the alu pipe.
__global__ __maxnreg__(32) void aq_hash() {
    const uint32_t base = blockIdx.x * 8192u + threadIdx.x;
#pragma unroll 4
    for (int r = 0; r < 32; r++) {
        uint32_t e = base + (uint32_t)r * 256u;
        uint32_t o0, o1;
        threefry42(0u, e, o0, o1);
        uint32_t bits = o0 ^ o1;
        float f = __uint_as_float((bits >> 9) | 0x3f800000u) - 1.0f;
        g_u[e] = f + 1.17549435e-38f;
    }
}

// --------------------- HMMA GEMM: logit = A x B^T ---------------------------
// CTA: 128 pixels x 128 codes, 8 warps (2m x 4n), each 64x32 via mma.m16n8k16.
// 3 fp16-split terms (a0b0, a0b1, a1b0) accumulate into fp32 C; epilogue /64.
// __maxnreg__(112): leaves 8192 regs so an aq_hash CTA co-resides per SM.
#define SROW      384
#define SM_A_OFF  0
#define SM_B_OFF  49152
#define SM_TOTAL  98304

__global__ __maxnreg__(112) void aq_gemm(float* __restrict__ logit) {
    extern __shared__ char smem[];
    const uint32_t sbase = smem_to_u32(smem);
    const int tid = threadIdx.x;
    const int l   = tid & 31;
    const int wid = tid >> 5;
    const int wm  = wid & 1;          // 2 m-warps (64 rows each)
    const int wn  = wid >> 1;         // 4 n-warps (32 cols each)
    const int n0   = blockIdx.x * 128;
    const int pix0 = blockIdx.y * 128;

    const __half* Asrc[2] = {g_A0, g_A1};
    const __half* Bsrc[2] = {g_B0, g_B1};
    const int TA[3] = {0, 0, 1};
    const int TB[3] = {0, 1, 0};

    float c[4][4][4];
#pragma unroll
    for (int mt = 0; mt < 4; mt++)
#pragma unroll
        for (int nt = 0; nt < 4; nt++)
#pragma unroll
            for (int r = 0; r < 4; r++) c[mt][nt][r] = 0.0f;

    auto load_tile = [&](const __half* src, uint32_t dbase) {
#pragma unroll
        for (int it = 0; it < 12; it++) {
            int e = it * 256 + tid;
            int row = e / 24, seg = e % 24;
            CP16(dbase + row * SROW + (seg ^ (row & 7)) * 16,
                 src + (size_t)row * NCH + seg * 8);
        }
    };

    load_tile(Asrc[0] + (size_t)pix0 * NCH, sbase + SM_A_OFF);
    load_tile(Bsrc[0] + (size_t)n0 * NCH, sbase + SM_B_OFF);
    CP_COMMIT();

    const int arow  = (l & 15);
    const int ahalf = l >> 4;
    const int brow  = ((l >> 4) * 8 + (l & 7));
    const int bhalf = (l >> 3) & 1;

    for (int t = 0; t < 3; t++) {
        CP_WAIT(0);
        __syncthreads();

#pragma unroll
        for (int ks = 0; ks < 12; ks++) {
            uint32_t a[4][4];
            uint32_t b[4][2];
#pragma unroll
            for (int mt = 0; mt < 4; mt++) {
                int row = wm * 64 + mt * 16 + arow;
                uint32_t addr = sbase + SM_A_OFF + row * SROW
                              + (((2 * ks + ahalf) ^ (row & 7)) * 16);
                LDSM_X4(a[mt][0], a[mt][1], a[mt][2], a[mt][3], addr);
            }
#pragma unroll
            for (int np = 0; np < 2; np++) {
                int row = wn * 32 + np * 16 + brow;
                uint32_t addr = sbase + SM_B_OFF + row * SROW
                              + (((2 * ks + bhalf) ^ (row & 7)) * 16);
                uint32_t r0, r1, r2, r3;
                LDSM_X4(r0, r1, r2, r3, addr);
                b[2 * np][0] = r0;     b[2 * np][1] = r1;
                b[2 * np + 1][0] = r2; b[2 * np + 1][1] = r3;
            }
#pragma unroll
            for (int mt = 0; mt < 4; mt++)
#pragma unroll
                for (int nt = 0; nt < 4; nt++)
                    MMA16816(c[mt][nt], a[mt], b[nt]);
        }

        if (t < 2) {
            __syncthreads();
            if (TA[t + 1] != TA[t])
                load_tile(Asrc[TA[t + 1]] + (size_t)pix0 * NCH, sbase + SM_A_OFF);
            load_tile(Bsrc[TB[t + 1]] + (size_t)n0 * NCH, sbase + SM_B_OFF);
            CP_COMMIT();
        }
    }

    // epilogue: descale (kk was x64) and store
#pragma unroll
    for (int mt = 0; mt < 4; mt++) {
#pragma unroll
        for (int nt = 0; nt < 4; nt++) {
            int row = pix0 + wm * 64 + mt * 16 + (l >> 2);
            int col = n0 + wn * 32 + nt * 8 + (l & 3) * 2;
            float* d = logit + (size_t)row * 1024 + col;
            *(float2*)d = make_float2(c[mt][nt][0] * 0.015625f,
                                      c[mt][nt][1] * 0.015625f);
            *(float2*)(d + 8 * 1024) = make_float2(c[mt][nt][2] * 0.015625f,
                                                   c[mt][nt][3] * 0.015625f);
        }
    }
}

// ------------- reduce: trueCode + gumbel argmax (memory-bound) -------------
__global__ __launch_bounds__(256) void aq_reduce(const float* __restrict__ logit,
                                                 float* __restrict__ out_tc) {
    const int p = blockIdx.x;
    const int t = threadIdx.x;
    const float* L = logit + (size_t)p * 1024;
    const float* U = g_u + (size_t)p * 1024;

    float l[4], u[4];
    float maxl = -1e30f, minl = 1e30f, maxu = 0.0f;
    unsigned long long ktrue = 0ull;
#pragma unroll
    for (int r = 0; r < 4; r++) {
        int j = t + r * 256;
        l[r] = __ldcs(&L[j]);
        u[r] = __ldcs(&U[j]);
        maxl = fmaxf(maxl, l[r]);
        minl = fminf(minl, l[r]);
        maxu = fmaxf(maxu, u[r]);
        unsigned long long k = packkey(l[r], j);
        if (k > ktrue) ktrue = k;
    }
#pragma unroll
    for (int s = 16; s; s >>= 1) {
        maxl = fmaxf(maxl, __shfl_xor_sync(0xffffffffu, maxl, s));
        minl = fminf(minl, __shfl_xor_sync(0xffffffffu, minl, s));
        maxu = fmaxf(maxu, __shfl_xor_sync(0xffffffffu, maxu, s));
        unsigned long long o = __shfl_xor_sync(0xffffffffu, ktrue, s);
        if (o > ktrue) ktrue = o;
    }
    __shared__ float s_maxl[8], s_minl[8], s_maxu[8];
    __shared__ unsigned long long s_k[8];
    __shared__ float s_th;
    __shared__ unsigned long long s_true;
    const int w = t >> 5;
    if ((t & 31) == 0) { s_maxl[w] = maxl; s_minl[w] = minl; s_maxu[w] = maxu; s_k[w] = ktrue; }
    __syncthreads();
    if (t == 0) {
        float Ml = s_maxl[0], ml = s_minl[0], Mu = s_maxu[0];
        unsigned long long kt = s_k[0];
#pragma unroll
        for (int i = 1; i < 8; i++) {
            Ml = fmaxf(Ml, s_maxl[i]);
            ml = fminf(ml, s_minl[i]);
            Mu = fmaxf(Mu, s_maxu[i]);
            if (s_k[i] > kt) kt = s_k[i];
        }
        s_true = kt;
        float gstar = gumbel_of_u(Mu);
        float gt = gstar - (Ml - ml) - 0.05f;
        float ee = expf(-gt);
        float th = (ee < 80.0f) ? (expf(-ee) - 1e-7f) : -1.0f;
        s_th = fminf(th, Mu);
    }
    __syncthreads();
    const float th = s_th;
    unsigned long long kpert = 0ull;
#pragma unroll
    for (int r = 0; r < 4; r++) {
        if (u[r] >= th) {
            float z = l[r] + gumbel_of_u(u[r]);
            unsigned long long k = packkey(z, t + r * 256);
            if (k > kpert) kpert = k;
        }
    }
#pragma unroll
    for (int s = 16; s; s >>= 1) {
        unsigned long long o = __shfl_xor_sync(0xffffffffu, kpert, s);
        if (o > kpert) kpert = o;
    }
    if ((t & 31) == 0) s_k[w] = kpert;
    __syncthreads();
    if (t == 0) {
        unsigned long long kp = s_k[0];
#pragma unroll
        for (int i = 1; i < 8; i++) if (s_k[i] > kp) kp = s_k[i];
        out_tc[p] = (float)(1023 - (int)(s_true & 0xFFFFFFFFull));
        g_idx[p]  = 1023 - (int)(kp & 0xFFFFFFFFull);
    }
}

// ---------------------- gather: quantized = v[idx] -------------------------
__global__ __launch_bounds__(256) void aq_gather(float* __restrict__ out_q) {
    const int nc = blockIdx.x;
    const int n  = nc / NCH;
    const int c  = nc % NCH;
    const int pbase = n * 4096;
    for (int hw = threadIdx.x; hw < 4096; hw += 256) {
        int idx = g_idx[pbase + hw];
        out_q[(size_t)nc * 4096 + hw] = g_v[(size_t)idx * NCH + c];
    }
}

// ----------------------------- launch --------------------------------------
struct AqResources {
    cudaStream_t s2;
    cudaEvent_t fork, convDone, hashDone;
    AqResources() {
        cudaStreamCreateWithFlags(&s2, cudaStreamNonBlocking);
        cudaEventCreateWithFlags(&fork, cudaEventDisableTiming);
        cudaEventCreateWithFlags(&convDone, cudaEventDisableTiming);
        cudaEventCreateWithFlags(&hashDone, cudaEventDisableTiming);
        cudaFuncSetAttribute(aq_gemm, cudaFuncAttributeMaxDynamicSharedMemorySize,
                             SM_TOTAL);
    }
};

extern "C" void kernel_launch(void* const* d_in, const int* in_sizes, int n_in,
                              void* d_out, int out_size) {
    const float* latent   = (const float*)d_in[0];
    const float* codebook = (const float*)d_in[1];
    const float* wq       = (const float*)d_in[2];
    const float* wk       = (const float*)d_in[3];
    const float* wv       = (const float*)d_in[4];
    const float* t1       = (const float*)d_in[5];
    // d_in[6] = temperature (int, ==1): argmax-invariant, ignored.

    float* out       = (float*)d_out;
    float* out_q     = out;                              // 8*192*64*64
    float* out_tc    = out + (size_t)NIMG * NCH * 4096;  // 32768
    float* out_logit = out_tc + NPIX;                    // 32768*1024

    static AqResources R;   // created on first (uncaptured) call

    // fork side stream from the main stream
    cudaEventRecord(R.fork, 0);
    cudaStreamWaitEvent(R.s2, R.fork, 0);

    // s2: convA then dependency-free hash (overlaps the gemm on main)
    aq_convA<<<dim3(128, 6, 8), dim3(32, 8), 0, R.s2>>>(latent);
    cudaEventRecord(R.convDone, R.s2);
    aq_hash<<<NELEM / 8192, 256, 0, R.s2>>>();
    cudaEventRecord(R.hashDone, R.s2);

    // main: preps, then monolithic gemm (needs convA + preps)
    aq_prep1<<<NCH, NCH>>>(wq, wk, wv, t1);
    aq_prep2<<<KCODES / 8, NCH>>>(codebook);
    cudaStreamWaitEvent(0, R.convDone, 0);
    aq_gemm<<<dim3(8, 256), 256, SM_TOTAL>>>(out_logit);

    // reduce needs gemm (main-stream ordered) + hash
    cudaStreamWaitEvent(0, R.hashDone, 0);
    aq_reduce<<<NPIX, 256>>>(out_logit, out_tc);
    aq_gather<<<NIMG * NCH, 256>>>(out_q);
}

// round 16
// speedup vs baseline: 1.1015x; 1.1015x over previous
#include <cuda_runtime.h>
#include <cuda_bf16.h>
#include <cuda_fp16.h>
#include <cstdint>
#include <cstddef>

#define NIMG    8
#define NCH     192
#define KCODES  1024
#define NPIX    32768
#define NCHUNK  8
#define CHPIX   (NPIX / NCHUNK)     // 4096 pixels per chunk

// ----------------------------- device scratch ------------------------------
__device__ __align__(256) float g_B[NCH * NCH];     // (wk^T wq) * t1/sqrt(192), [c'][c]
__device__ __align__(256) float g_wvT[NCH * NCH];   // wv transposed: [c'][o]
__device__ __align__(256) float g_v[KCODES * NCH];  // value matrix [j][o]
__device__ int g_idx[NPIX];                         // gumbel argmax per pixel

// fp16 2-way mantissa splits (A = latent, B = kk * 64)
__device__ __align__(256) __half g_A0[NPIX * NCH];
__device__ __align__(256) __half g_A1[NPIX * NCH];
__device__ __align__(256) __half g_B0[KCODES * NCH];
__device__ __align__(256) __half g_B1[KCODES * NCH];

// ----------------------------- PTX helpers (baseline ISA only) -------------
__device__ __forceinline__ uint32_t smem_to_u32(const void* p) {
    uint32_t a;
    asm("{ .reg .u64 t; cvta.to.shared.u64 t, %1; cvt.u32.u64 %0, t; }" : "=r"(a) : "l"(p));
    return a;
}
#define LDSM_X4(r0, r1, r2, r3, addr) \
    asm volatile("ldmatrix.sync.aligned.m8n8.x4.shared.b16 {%0,%1,%2,%3}, [%4];" \
        : "=r"(r0), "=r"(r1), "=r"(r2), "=r"(r3) : "r"(addr))
#define MMA16816(c, a, b) \
    asm volatile("mma.sync.aligned.m16n8k16.row.col.f32.f16.f16.f32 " \
        "{%0,%1,%2,%3},{%4,%5,%6,%7},{%8,%9},{%0,%1,%2,%3};" \
        : "+f"((c)[0]), "+f"((c)[1]), "+f"((c)[2]), "+f"((c)[3]) \
        : "r"((a)[0]), "r"((a)[1]), "r"((a)[2]), "r"((a)[3]), "r"((b)[0]), "r"((b)[1]))
#define CP16(dst, src) \
    asm volatile("cp.async.cg.shared.global [%0], [%1], 16;" :: "r"(dst), "l"(src))
#define CP_COMMIT() asm volatile("cp.async.commit_group;" ::: "memory")
#define CP_WAIT(n)  asm volatile("cp.async.wait_group %0;" :: "n"(n) : "memory")

// ----------------------------- math helpers --------------------------------
// Threefry-2x32, 20 rounds, key = (0, 42)
__device__ __forceinline__ void threefry42(uint32_t c0, uint32_t c1,
                                           uint32_t& o0, uint32_t& o1) {
    const uint32_t ks0 = 0u;
    const uint32_t ks1 = 42u;
    const uint32_t ks2 = 0x1BD11BDAu ^ 42u;
    uint32_t x0 = c0 + ks0;
    uint32_t x1 = c1 + ks1;
#define TFR(r) { x0 += x1; x1 = __funnelshift_l(x1, x1, (r)); x1 ^= x0; }
    TFR(13) TFR(15) TFR(26) TFR(6)
    x0 += ks1; x1 += ks2 + 1u;
    TFR(17) TFR(29) TFR(16) TFR(24)
    x0 += ks2; x1 += ks0 + 2u;
    TFR(13) TFR(15) TFR(26) TFR(6)
    x0 += ks0; x1 += ks1 + 3u;
    TFR(17) TFR(29) TFR(16) TFR(24)
    x0 += ks1; x1 += ks2 + 4u;
    TFR(13) TFR(15) TFR(26) TFR(6)
    x0 += ks2; x1 += ks0 + 5u;
#undef TFR
    o0 = x0; o1 = x1;
}
__device__ __forceinline__ float gumbel_of_u(float u) {
    float w = -log1pf(u - 1.0f);
    return -logf(w);
}
__device__ __forceinline__ unsigned long long packkey(float v, int j) {
    uint32_t u = __float_as_uint(v);
    u = ((int)u >= 0) ? (u | 0x80000000u) : ~u;
    return ((unsigned long long)u << 32) | (uint32_t)(1023 - j);
}
__device__ __forceinline__ void split2h(float a, __half& h0, __half& h1) {
    h0 = __float2half_rn(a);
    float r = a - __half2float(h0);
    h1 = __float2half_rn(r);
}

// ----------------------------- prep kernels --------------------------------
// B[c'][c] = s * sum_o wk[o][c'] * wq[o][c]; latency-optimized: 4-way o-unroll
// (8 batched loads -> MLP 8, 4 independent FMA chains).
__global__ __launch_bounds__(192) void aq_prep1(const float* __restrict__ wq,
                                                const float* __restrict__ wk,
                                                const float* __restrict__ wv,
                                                const float* __restrict__ t1) {
    const int cp = blockIdx.x;
    const int c  = threadIdx.x;
    const float s = t1[0] / 13.856406460551018f;  // t1 / sqrt(192)
    float acc0 = 0.0f, acc1 = 0.0f, acc2 = 0.0f, acc3 = 0.0f;
#pragma unroll 4
    for (int o = 0; o < NCH; o += 4) {
        float k0 = wk[(o + 0) * NCH + cp];
        float k1 = wk[(o + 1) * NCH + cp];
        float k2 = wk[(o + 2) * NCH + cp];
        float k3 = wk[(o + 3) * NCH + cp];
        float q0 = wq[(o + 0) * NCH + c];
        float q1 = wq[(o + 1) * NCH + c];
        float q2 = wq[(o + 2) * NCH + c];
        float q3 = wq[(o + 3) * NCH + c];
        acc0 = fmaf(k0, q0, acc0);
        acc1 = fmaf(k1, q1, acc1);
        acc2 = fmaf(k2, q2, acc2);
        acc3 = fmaf(k3, q3, acc3);
    }
    g_B[cp * NCH + c]   = ((acc0 + acc1) + (acc2 + acc3)) * s;
    g_wvT[cp * NCH + c] = wv[c * NCH + cp];
}

// kk = codebook @ B, scaled x64, emitted as fp16 splits; v = codebook @ wv^T.
// 256 CTAs x 4 rows; cp unrolled by 4 (8 batched loads, 8 FMA chains).
__global__ __launch_bounds__(192) void aq_prep2(const float* __restrict__ codebook) {
    __shared__ float cb[4][NCH];
    const int j0 = blockIdx.x * 4;
    const int t  = threadIdx.x;
    for (int idx = t; idx < 4 * NCH; idx += 192) {
        int r = idx / NCH, c = idx % NCH;
        cb[r][c] = codebook[(size_t)(j0 + r) * NCH + c];
    }
    __syncthreads();
    float a1[4], a2[4];
#pragma unroll
    for (int r = 0; r < 4; r++) { a1[r] = 0.0f; a2[r] = 0.0f; }
#pragma unroll 4
    for (int cp = 0; cp < NCH; cp += 4) {
        float b0 = g_B[(cp + 0) * NCH + t];
        float b1 = g_B[(cp + 1) * NCH + t];
        float b2 = g_B[(cp + 2) * NCH + t];
        float b3 = g_B[(cp + 3) * NCH + t];
        float w0 = g_wvT[(cp + 0) * NCH + t];
        float w1 = g_wvT[(cp + 1) * NCH + t];
        float w2 = g_wvT[(cp + 2) * NCH + t];
        float w3 = g_wvT[(cp + 3) * NCH + t];
#pragma unroll
        for (int r = 0; r < 4; r++) {
            a1[r] = fmaf(cb[r][cp + 0], b0, a1[r]);
            a1[r] = fmaf(cb[r][cp + 1], b1, a1[r]);
            a1[r] = fmaf(cb[r][cp + 2], b2, a1[r]);
            a1[r] = fmaf(cb[r][cp + 3], b3, a1[r]);
            a2[r] = fmaf(cb[r][cp + 0], w0, a2[r]);
            a2[r] = fmaf(cb[r][cp + 1], w1, a2[r]);
            a2[r] = fmaf(cb[r][cp + 2], w2, a2[r]);
            a2[r] = fmaf(cb[r][cp + 3], w3, a2[r]);
        }
    }
#pragma unroll
    for (int r = 0; r < 4; r++) {
        size_t o = (size_t)(j0 + r) * NCH + t;
        __half s0, s1;
        split2h(a1[r] * 64.0f, s0, s1);   // scale keeps s1 in fp16 normal range
        g_B0[o] = s0; g_B1[o] = s1;
        g_v[o] = a2[r];
    }
}

// transpose + split: latent [n][c][hw] fp32 -> g_A{0,1} [p][c] fp16
__global__ __launch_bounds__(256) void aq_convA(const float* __restrict__ latent) {
    __shared__ float tile[32][33];
    const int hw0 = blockIdx.x * 32;
    const int c0  = blockIdx.y * 32;
    const int n   = blockIdx.z;
    const int tx  = threadIdx.x;       // 0..31
    const int ty  = threadIdx.y;       // 0..7
#pragma unroll
    for (int k = 0; k < 4; k++) {
        int c = c0 + ty + k * 8;
        tile[ty + k * 8][tx] = latent[((size_t)n * NCH + c) * 4096 + hw0 + tx];
    }
    __syncthreads();
#pragma unroll
    for (int k = 0; k < 4; k++) {
        int hw = hw0 + ty + k * 8;
        size_t o = (size_t)(n * 4096 + hw) * NCH + c0 + tx;
        __half s0, s1;
        split2h(tile[tx][ty + k * 8], s0, s1);
        g_A0[o] = s0; g_A1[o] = s1;
    }
}

// --------------------- HMMA GEMM: logit = A x B^T ---------------------------
// CTA: 128 pixels x 128 codes, 8 warps (2m x 4n), each 64x32 via mma.m16n8k16.
// 3 fp16-split terms (a0b0, a0b1, a1b0) accumulate into fp32 C; epilogue /64.
#define SROW      384
#define SM_A_OFF  0
#define SM_B_OFF  49152
#define SM_TOTAL  98304

__global__ __launch_bounds__(256, 2) void aq_gemm(float* __restrict__ logit,
                                                  int pbase) {
    extern __shared__ char smem[];
    const uint32_t sbase = smem_to_u32(smem);
    const int tid = threadIdx.x;
    const int l   = tid & 31;
    const int wid = tid >> 5;
    const int wm  = wid & 1;          // 2 m-warps (64 rows each)
    const int wn  = wid >> 1;         // 4 n-warps (32 cols each)
    const int n0   = blockIdx.x * 128;
    const int pix0 = pbase + blockIdx.y * 128;

    const __half* Asrc[2] = {g_A0, g_A1};
    const __half* Bsrc[2] = {g_B0, g_B1};
    const int TA[3] = {0, 0, 1};
    const int TB[3] = {0, 1, 0};

    float c[4][4][4];
#pragma unroll
    for (int mt = 0; mt < 4; mt++)
#pragma unroll
        for (int nt = 0; nt < 4; nt++)
#pragma unroll
            for (int r = 0; r < 4; r++) c[mt][nt][r] = 0.0f;

    auto load_tile = [&](const __half* src, uint32_t dbase) {
#pragma unroll
        for (int it = 0; it < 12; it++) {
            int e = it * 256 + tid;
            int row = e / 24, seg = e % 24;
            CP16(dbase + row * SROW + (seg ^ (row & 7)) * 16,
                 src + (size_t)row * NCH + seg * 8);
        }
    };

    load_tile(Asrc[0] + (size_t)pix0 * NCH, sbase + SM_A_OFF);
    load_tile(Bsrc[0] + (size_t)n0 * NCH, sbase + SM_B_OFF);
    CP_COMMIT();

    const int arow  = (l & 15);
    const int ahalf = l >> 4;
    const int brow  = ((l >> 4) * 8 + (l & 7));
    const int bhalf = (l >> 3) & 1;

    for (int t = 0; t < 3; t++) {
        CP_WAIT(0);
        __syncthreads();

#pragma unroll
        for (int ks = 0; ks < 12; ks++) {
            uint32_t a[4][4];
            uint32_t b[4][2];
#pragma unroll
            for (int mt = 0; mt < 4; mt++) {
                int row = wm * 64 + mt * 16 + arow;
                uint32_t addr = sbase + SM_A_OFF + row * SROW
                              + (((2 * ks + ahalf) ^ (row & 7)) * 16);
                LDSM_X4(a[mt][0], a[mt][1], a[mt][2], a[mt][3], addr);
            }
#pragma unroll
            for (int np = 0; np < 2; np++) {
                int row = wn * 32 + np * 16 + brow;
                uint32_t addr = sbase + SM_B_OFF + row * SROW
                              + (((2 * ks + bhalf) ^ (row & 7)) * 16);
                uint32_t r0, r1, r2, r3;
                LDSM_X4(r0, r1, r2, r3, addr);
                b[2 * np][0] = r0;     b[2 * np][1] = r1;
                b[2 * np + 1][0] = r2; b[2 * np + 1][1] = r3;
            }
#pragma unroll
            for (int mt = 0; mt < 4; mt++)
#pragma unroll
                for (int nt = 0; nt < 4; nt++)
                    MMA16816(c[mt][nt], a[mt], b[nt]);
        }

        if (t < 2) {
            __syncthreads();
            if (TA[t + 1] != TA[t])
                load_tile(Asrc[TA[t + 1]] + (size_t)pix0 * NCH, sbase + SM_A_OFF);
            load_tile(Bsrc[TB[t + 1]] + (size_t)n0 * NCH, sbase + SM_B_OFF);
            CP_COMMIT();
        }
    }

    // epilogue: descale (kk was x64) and store
#pragma unroll
    for (int mt = 0; mt < 4; mt++) {
#pragma unroll
        for (int nt = 0; nt < 4; nt++) {
            int row = pix0 + wm * 64 + mt * 16 + (l >> 2);
            int col = n0 + wn * 32 + nt * 8 + (l & 3) * 2;
            float* d = logit + (size_t)row * 1024 + col;
            *(float2*)d = make_float2(c[mt][nt][0] * 0.015625f,
                                      c[mt][nt][1] * 0.015625f);
            *(float2*)(d + 8 * 1024) = make_float2(c[mt][nt][2] * 0.015625f,
                                                   c[mt][nt][3] * 0.015625f);
        }
    }
}

// ------------------- reduce: trueCode + gumbel argmax ----------------------
__global__ __launch_bounds__(256) void aq_reduce(const float* __restrict__ logit,
                                                 float* __restrict__ out_tc,
                                                 int pbase) {
    const int p = pbase + blockIdx.x;
    const int t = threadIdx.x;
    const float* L = logit + (size_t)p * 1024;
    const uint32_t cbase = (uint32_t)p << 10;

    float l[4], u[4];
    float maxl = -1e30f, minl = 1e30f, maxu = 0.0f;
    unsigned long long ktrue = 0ull;
#pragma unroll
    for (int r = 0; r < 4; r++) {
        int j = t + r * 256;
        l[r] = __ldcs(&L[j]);          // streaming: don't pollute L2 under gemm
        uint32_t o0, o1;
        threefry42(0u, cbase + (uint32_t)j, o0, o1);
        uint32_t bits = o0 ^ o1;
        float f = __uint_as_float((bits >> 9) | 0x3f800000u) - 1.0f;
        u[r] = f + 1.17549435e-38f;
        maxl = fmaxf(maxl, l[r]);
        minl = fminf(minl, l[r]);
        maxu = fmaxf(maxu, u[r]);
        unsigned long long k = packkey(l[r], j);
        if (k > ktrue) ktrue = k;
    }
#pragma unroll
    for (int s = 16; s; s >>= 1) {
        maxl = fmaxf(maxl, __shfl_xor_sync(0xffffffffu, maxl, s));
        minl = fminf(minl, __shfl_xor_sync(0xffffffffu, minl, s));
        maxu = fmaxf(maxu, __shfl_xor_sync(0xffffffffu, maxu, s));
        unsigned long long o = __shfl_xor_sync(0xffffffffu, ktrue, s);
        if (o > ktrue) ktrue = o;
    }
    __shared__ float s_maxl[8], s_minl[8], s_maxu[8];
    __shared__ unsigned long long s_k[8];
    __shared__ float s_th;
    __shared__ unsigned long long s_true;
    const int w = t >> 5;
    if ((t & 31) == 0) { s_maxl[w] = maxl; s_minl[w] = minl; s_maxu[w] = maxu; s_k[w] = ktrue; }
    __syncthreads();
    if (t == 0) {
        float Ml = s_maxl[0], ml = s_minl[0], Mu = s_maxu[0];
        unsigned long long kt = s_k[0];
#pragma unroll
        for (int i = 1; i < 8; i++) {
            Ml = fmaxf(Ml, s_maxl[i]);
            ml = fminf(ml, s_minl[i]);
            Mu = fmaxf(Mu, s_maxu[i]);
            if (s_k[i] > kt) kt = s_k[i];
        }
        s_true = kt;
        float gstar = gumbel_of_u(Mu);
        float gt = gstar - (Ml - ml) - 0.05f;
        float ee = expf(-gt);
        float th = (ee < 80.0f) ? (expf(-ee) - 1e-7f) : -1.0f;
        s_th = fminf(th, Mu);
    }
    __syncthreads();
    const float th = s_th;
    unsigned long long kpert = 0ull;
#pragma unroll
    for (int r = 0; r < 4; r++) {
        if (u[r] >= th) {
            float z = l[r] + gumbel_of_u(u[r]);
            unsigned long long k = packkey(z, t + r * 256);
            if (k > kpert) kpert = k;
        }
    }
#pragma unroll
    for (int s = 16; s; s >>= 1) {
        unsigned long long o = __shfl_xor_sync(0xffffffffu, kpert, s);
        if (o > kpert) kpert = o;
    }
    if ((t & 31) == 0) s_k[w] = kpert;
    __syncthreads();
    if (t == 0) {
        unsigned long long kp = s_k[0];
#pragma unroll
        for (int i = 1; i < 8; i++) if (s_k[i] > kp) kp = s_k[i];
        out_tc[p] = (float)(1023 - (int)(s_true & 0xFFFFFFFFull));
        g_idx[p]  = 1023 - (int)(kp & 0xFFFFFFFFull);
    }
}

// ---------------------- gather: quantized = v[idx] -------------------------
__global__ __launch_bounds__(256) void aq_gather(float* __restrict__ out_q) {
    const int nc = blockIdx.x;
    const int n  = nc / NCH;
    const int c  = nc % NCH;
    const int pbase = n * 4096;
    for (int hw = threadIdx.x; hw < 4096; hw += 256) {
        int idx = g_idx[pbase + hw];
        out_q[(size_t)nc * 4096 + hw] = g_v[(size_t)idx * NCH + c];
    }
}

// ----------------------------- launch --------------------------------------
struct AqResources {
    cudaStream_t s2;
    cudaEvent_t fork, convDone, gDone[NCHUNK], rDone;
    AqResources() {
        cudaStreamCreateWithFlags(&s2, cudaStreamNonBlocking);
        cudaEventCreateWithFlags(&fork, cudaEventDisableTiming);
        cudaEventCreateWithFlags(&convDone, cudaEventDisableTiming);
        for (int i = 0; i < NCHUNK; i++)
            cudaEventCreateWithFlags(&gDone[i], cudaEventDisableTiming);
        cudaEventCreateWithFlags(&rDone, cudaEventDisableTiming);
        cudaFuncSetAttribute(aq_gemm, cudaFuncAttributeMaxDynamicSharedMemorySize,
                             SM_TOTAL);
    }
};

extern "C" void kernel_launch(void* const* d_in, const int* in_sizes, int n_in,
                              void* d_out, int out_size) {
    const float* latent   = (const float*)d_in[0];
    const float* codebook = (const float*)d_in[1];
    const float* wq       = (const float*)d_in[2];
    const float* wk       = (const float*)d_in[3];
    const float* wv       = (const float*)d_in[4];
    const float* t1       = (const float*)d_in[5];
    // d_in[6] = temperature (int, ==1): argmax-invariant, ignored.

    float* out       = (float*)d_out;
    float* out_q     = out;                              // 8*192*64*64
    float* out_tc    = out + (size_t)NIMG * NCH * 4096;  // 32768
    float* out_logit = out_tc + NPIX;                    // 32768*1024

    static AqResources R;   // created on first (uncaptured) call

    // fork side stream from the main stream
    cudaEventRecord(R.fork, 0);
    cudaStreamWaitEvent(R.s2, R.fork, 0);

    // convA (monolithic) on s2, preps on main stream (independent)
    aq_convA<<<dim3(128, 6, 8), dim3(32, 8), 0, R.s2>>>(latent);
    cudaEventRecord(R.convDone, R.s2);

    aq_prep1<<<NCH, NCH>>>(wq, wk, wv, t1);
    aq_prep2<<<KCODES / 4, NCH>>>(codebook);
    cudaStreamWaitEvent(0, R.convDone, 0);

    // chunked gemm (main stream) overlapped with reduce (s2)
    for (int k = 0; k < NCHUNK; k++) {
        aq_gemm<<<dim3(8, CHPIX / 128), 256, SM_TOTAL>>>(out_logit, k * CHPIX);
        cudaEventRecord(R.gDone[k], 0);
        cudaStreamWaitEvent(R.s2, R.gDone[k], 0);
        aq_reduce<<<CHPIX, 256, 0, R.s2>>>(out_logit, out_tc, k * CHPIX);
    }
    cudaEventRecord(R.rDone, R.s2);
    cudaStreamWaitEvent(0, R.rDone, 0);

    aq_gather<<<NIMG * NCH, 256>>>(out_q);
}